// round 16
// baseline (speedup 1.0000x reference)
#include <cuda_runtime.h>
#include <cstdint>

#define NT     256
#define PPT    7
#define NTCH   8
#define MAXT   512
#define MAXP   65536
#define NWARP  (NT / 32)
#define PPB    (NT * PPT)   // 1792 priors per block
#define TCHMAX 64
#define FULLM  0xffffffffu

// Scratch — zero-initialized at module load; every call restores zeros itself.
__device__ unsigned long long g_best[MAXT];     // per-truth packed (r_bits<<32 | ~p_thread)
__device__ unsigned long long g_scatter[MAXP];  // per-prior packed ((t+1)<<32 | iou_bits)
__device__ unsigned           g_bto[MAXP];      // per-prior max r (float bits, >=0)
__device__ float              g_sums[3];
__device__ unsigned           g_ctr_main;
__device__ unsigned           g_ctr_red;

__global__ void __launch_bounds__(NT, 2)
k_main(const float2* __restrict__ locs,
       const float*  __restrict__ params,
       const float4* __restrict__ truths,
       int P, int T, int pblocks, int tch, int nblocks) {
    __shared__ float4 s_tr[TCHMAX];
    __shared__ float  s_ta[TCHMAX];
    __shared__ unsigned long long s_best[TCHMAX * NWARP];
    __shared__ bool   s_last;

    const int pb  = blockIdx.x % pblocks;
    const int tc  = blockIdx.x / pblocks;
    const int t0  = tc * tch;
    const int t1  = min(min(t0 + tch, T), t0 + TCHMAX);
    const int tid = threadIdx.x;
    const int lane = tid & 31;
    const int wid  = tid >> 5;

    for (int t = t0 + tid; t < t1; t += NT) {
        float4 tb = truths[t];
        s_tr[t - t0] = tb;
        s_ta[t - t0] = (tb.z - tb.x) * (tb.w - tb.y);
    }
    __syncthreads();

    const int pbase = pb * PPB + tid;

    float x0[PPT], y0[PPT], x1[PPT], y1[PPT], ab[PPT], br[PPT];
#pragma unroll
    for (int j = 0; j < PPT; j++) {
        int p = pbase + j * NT;
        float cx, cy, w, h;
        if (p < P) {
            float2 c = locs[p];
            cx = c.x; cy = c.y;
            w = params[3 * p];
            h = params[3 * p + 1];
        } else {
            cx = -1e3f; cy = -1e3f; w = 0.0f; h = 0.0f;
        }
        x0[j] = cx - 0.5f * w;  x1[j] = cx + 0.5f * w;
        y0[j] = cy - 0.5f * h;  y1[j] = cy + 0.5f * h;
        ab[j] = w * h;
        br[j] = 0.0f;           // max r over t (r = inter/S, monotone in iou)
    }

    // ---- main loop: TWO truths per iteration for ILP (chains interleave) ----
    int tt = t0;
    for (; tt + 1 < t1; tt += 2) {
        const float4 tb0 = s_tr[tt - t0];
        const float4 tb1 = s_tr[tt - t0 + 1];
        const float  ta0 = s_ta[tt - t0];
        const float  ta1 = s_ta[tt - t0 + 1];

        float btr0 = 0.0f, btr1 = 0.0f;

#pragma unroll
        for (int j = 0; j < PPT; j++) {
            float dx0 = fminf(x1[j], tb0.z) - fmaxf(x0[j], tb0.x);
            float dy0 = fminf(y1[j], tb0.w) - fmaxf(y0[j], tb0.y);
            float dx1 = fminf(x1[j], tb1.z) - fmaxf(x0[j], tb1.x);
            float dy1 = fminf(y1[j], tb1.w) - fmaxf(y0[j], tb1.y);
            // single clamp: negative dy makes the product <=0, filtered by maxes
            float i0 = fmaxf(dx0, 0.0f) * dy0;
            float i1 = fmaxf(dx1, 0.0f) * dy1;
            float r0 = __fdividef(i0, ta0 + ab[j]);
            float r1 = __fdividef(i1, ta1 + ab[j]);
            br[j] = fmaxf(br[j], fmaxf(r0, r1));
            btr0  = fmaxf(btr0, r0);
            btr1  = fmaxf(btr1, r1);
        }

        // two interleaved warp maxes (independent chains)
        float a0 = btr0, a1 = btr1;
#pragma unroll
        for (int off = 16; off > 0; off >>= 1) {
            a0 = fmaxf(a0, __shfl_xor_sync(FULLM, a0, off));
            a1 = fmaxf(a1, __shfl_xor_sync(FULLM, a1, off));
        }
        unsigned b0 = __ballot_sync(FULLM, btr0 == a0);
        unsigned b1 = __ballot_sync(FULLM, btr1 == a1);
        if (lane == 0) {
            int base = pb * PPB + wid * 32;
            int pth0 = base + (__ffs(b0) - 1);
            int pth1 = base + (__ffs(b1) - 1);
            s_best[(tt - t0) * NWARP + wid] =
                (((unsigned long long)__float_as_uint(a0)) << 32) | (unsigned)(~pth0);
            s_best[(tt - t0 + 1) * NWARP + wid] =
                (((unsigned long long)__float_as_uint(a1)) << 32) | (unsigned)(~pth1);
        }
    }
    // odd tail
    for (; tt < t1; ++tt) {
        const float4 tb = s_tr[tt - t0];
        const float  ta = s_ta[tt - t0];
        float btr = 0.0f;
#pragma unroll
        for (int j = 0; j < PPT; j++) {
            float dx = fminf(x1[j], tb.z) - fmaxf(x0[j], tb.x);
            float dy = fminf(y1[j], tb.w) - fmaxf(y0[j], tb.y);
            float inter = fmaxf(dx, 0.0f) * dy;
            float r = __fdividef(inter, ta + ab[j]);
            br[j] = fmaxf(br[j], r);
            btr   = fmaxf(btr, r);
        }
        float mybtr = btr;
#pragma unroll
        for (int off = 16; off > 0; off >>= 1)
            btr = fmaxf(btr, __shfl_xor_sync(FULLM, btr, off));
        unsigned ball = __ballot_sync(FULLM, mybtr == btr);
        if (lane == 0) {
            int pth = pb * PPB + wid * 32 + (__ffs(ball) - 1);
            s_best[(tt - t0) * NWARP + wid] =
                (((unsigned long long)__float_as_uint(btr)) << 32) | (unsigned)(~pth);
        }
    }
    __syncthreads();

    // block combine + one global atomic per truth per block
    for (int t = t0 + tid; t < t1; t += NT) {
        unsigned long long m = s_best[(t - t0) * NWARP];
#pragma unroll
        for (int w = 1; w < NWARP; w++) {
            unsigned long long v = s_best[(t - t0) * NWARP + w];
            if (v > m) m = v;
        }
        atomicMax(&g_best[t], m);
    }

    // per-prior best overlap via float-bits atomicMax (values >= 0)
#pragma unroll
    for (int j = 0; j < PPT; j++) {
        int p = pbase + j * NT;
        if (p < P) atomicMax(&g_bto[p], __float_as_uint(br[j]));
    }

    // ---- last block: resolve j + exact iou + last-t-wins scatter ----
    __threadfence();
    if (tid == 0)
        s_last = (atomicAdd(&g_ctr_main, 1u) == (unsigned)(nblocks - 1));
    __syncthreads();
    if (s_last) {
        __threadfence();
        for (int t = tid; t < T; t += NT) {
            unsigned long long m = g_best[t];
            unsigned int pth = (~((unsigned int)(m & 0xffffffffull))) & (MAXP - 1u);
            g_best[t] = 0ull;                      // restore zeros for next call
            float4 tb = truths[t];
            float ta = (tb.z - tb.x) * (tb.w - tb.y);
            // resolve j among the winning thread's PPT priors (smallest-j ties)
            float best_r = -1.0f, best_iou = 0.0f;
            unsigned best_p = pth;
#pragma unroll
            for (int j = 0; j < PPT; j++) {
                unsigned p = pth + (unsigned)(j * NT);
                if (p < (unsigned)P) {
                    float2 c = locs[p];
                    float w = params[3 * p];
                    float h = params[3 * p + 1];
                    float dx = fminf(c.x + 0.5f * w, tb.z) - fmaxf(c.x - 0.5f * w, tb.x);
                    float dy = fminf(c.y + 0.5f * h, tb.w) - fmaxf(c.y - 0.5f * h, tb.y);
                    float inter = fmaxf(dx, 0.0f) * fmaxf(dy, 0.0f);
                    float S = ta + w * h;
                    float r = inter / S;                       // exact
                    if (r > best_r) {
                        best_r = r;
                        best_p = p;
                        best_iou = inter / (S - inter);        // exact iou
                    }
                }
            }
            atomicMax(&g_scatter[best_p],
                (((unsigned long long)(t + 1)) << 32) | __float_as_uint(best_iou));
        }
        if (tid == 0) g_ctr_main = 0u;             // restore for next call
    }
}

__global__ void __launch_bounds__(NT)
k_reduce(const float* __restrict__ params,
         float* __restrict__ out, int P, int nblocks) {
    __shared__ float sh0[NWARP], sh1[NWARP], sh2[NWARP];
    __shared__ bool  s_last;
    const int tid  = threadIdx.x;
    const int lane = tid & 31;
    const int wid  = tid >> 5;
    const int p    = blockIdx.x * NT + tid;

    // ---- PDL preamble: runs while k_main is still executing ----
    float sig = 0.0f;
    if (p < P) {
        float a = params[3 * p + 2];               // input array: safe pre-sync
        sig = 1.0f / (1.0f + __expf(-a));
    }

    // Wait for k_main completion (no early trigger in k_main => full completion)
    cudaGridDependencySynchronize();

    float s0 = 0.0f, s1 = 0.0f, s2 = 0.0f;
    if (p < P) {
        unsigned rb = g_bto[p];
        unsigned long long sc = g_scatter[p];
        g_bto[p] = 0u;                             // restore zeros for next call
        float r   = __uint_as_float(rb);
        float bto = __fdividef(r, 1.0f - r);       // r <= 0.5 always
        bool isbest = (sc != 0ull);
        if (isbest) {
            bto = __uint_as_float((unsigned int)(sc & 0xffffffffull));
            g_scatter[p] = 0ull;                   // restore zeros for next call
        }
        float xf = isbest ? 5.0f : (bto > 0.5f ? 1.0f : 0.0f);
        s0 = sig * xf * bto;
        s1 = sig;          // BETA = 1
        s2 = xf;
    }
#pragma unroll
    for (int off = 16; off > 0; off >>= 1) {
        s0 += __shfl_xor_sync(FULLM, s0, off);
        s1 += __shfl_xor_sync(FULLM, s1, off);
        s2 += __shfl_xor_sync(FULLM, s2, off);
    }
    if (lane == 0) { sh0[wid] = s0; sh1[wid] = s1; sh2[wid] = s2; }
    __syncthreads();
    if (wid == 0) {
        s0 = (lane < NWARP) ? sh0[lane] : 0.0f;
        s1 = (lane < NWARP) ? sh1[lane] : 0.0f;
        s2 = (lane < NWARP) ? sh2[lane] : 0.0f;
#pragma unroll
        for (int off = 4; off > 0; off >>= 1) {
            s0 += __shfl_xor_sync(FULLM, s0, off);
            s1 += __shfl_xor_sync(FULLM, s1, off);
            s2 += __shfl_xor_sync(FULLM, s2, off);
        }
        if (lane == 0) {
            atomicAdd(&g_sums[0], s0);
            atomicAdd(&g_sums[1], s1);
            atomicAdd(&g_sums[2], s2);
        }
    }

    __threadfence();
    if (tid == 0)
        s_last = (atomicAdd(&g_ctr_red, 1u) == (unsigned)(nblocks - 1));
    __syncthreads();
    if (s_last && tid == 0) {
        __threadfence();
        out[0] = (g_sums[0] + g_sums[1]) / g_sums[2];
        g_sums[0] = 0.0f; g_sums[1] = 0.0f; g_sums[2] = 0.0f;
        g_ctr_red = 0u;
    }
}

extern "C" void kernel_launch(void* const* d_in, const int* in_sizes, int n_in,
                              void* d_out, int out_size) {
    const float2* locs   = (const float2*)d_in[0];
    const float*  params = (const float*)d_in[1];
    const float4* truths = (const float4*)d_in[2];
    int P = in_sizes[0] / 2;
    int T = in_sizes[2] / 4;

    int tch     = (T + NTCH - 1) / NTCH;   // 64 for T=512
    int pblocks = (P + PPB - 1) / PPB;     // 37 for P=65536
    int nmain   = pblocks * NTCH;          // 296 = 148 SMs x occ 2 (single wave)

    k_main<<<nmain, NT>>>(locs, params, truths, P, T, pblocks, tch, nmain);

    // PDL launch: k_reduce blocks start early, preamble overlaps k_main,
    // cudaGridDependencySynchronize() enforces the data dependency.
    int nred = (P + NT - 1) / NT;          // 256 blocks, 1 prior/thread
    {
        cudaLaunchConfig_t cfg = {};
        cfg.gridDim  = dim3((unsigned)nred, 1, 1);
        cfg.blockDim = dim3(NT, 1, 1);
        cfg.dynamicSmemBytes = 0;
        cudaLaunchAttribute attrs[1];
        attrs[0].id = cudaLaunchAttributeProgrammaticStreamSerialization;
        attrs[0].val.programmaticStreamSerializationAllowed = 1;
        cfg.attrs = attrs;
        cfg.numAttrs = 1;
        cudaLaunchKernelEx(&cfg, k_reduce, params, (float*)d_out, P, nred);
    }
}

// round 17
// speedup vs baseline: 1.0476x; 1.0476x over previous
#include <cuda_runtime.h>
#include <cstdint>

#define NT     256
#define PPT    7
#define NTCH   12
#define MAXT   512
#define MAXP   65536
#define NWARP  (NT / 32)
#define PPB    (NT * PPT)   // 1792 priors per block
#define TCHMAX 64
#define FULLM  0xffffffffu

// Scratch — zero-initialized at module load; every call restores zeros itself.
__device__ unsigned long long g_best[MAXT];     // per-truth packed (r_bits<<32 | ~p_thread)
__device__ unsigned long long g_scatter[MAXP];  // per-prior packed ((t+1)<<32 | iou_bits)
__device__ unsigned           g_bto[MAXP];      // per-prior max r (float bits, >=0)
__device__ float              g_sums[3];
__device__ unsigned           g_ctr_main;
__device__ unsigned           g_ctr_red;

__global__ void __launch_bounds__(NT, 3)
k_main(const float2* __restrict__ locs,
       const float*  __restrict__ params,
       const float4* __restrict__ truths,
       int P, int T, int pblocks, int tch, int nblocks) {
    __shared__ float4 s_tr[TCHMAX];
    __shared__ float  s_ta[TCHMAX];
    __shared__ unsigned long long s_best[TCHMAX * NWARP];
    __shared__ bool   s_last;

    const int pb  = blockIdx.x % pblocks;
    const int tc  = blockIdx.x / pblocks;
    const int t0  = tc * tch;
    const int t1  = min(min(t0 + tch, T), t0 + TCHMAX);
    const int tid = threadIdx.x;
    const int lane = tid & 31;
    const int wid  = tid >> 5;

    for (int t = t0 + tid; t < t1; t += NT) {
        float4 tb = truths[t];
        s_tr[t - t0] = tb;
        s_ta[t - t0] = (tb.z - tb.x) * (tb.w - tb.y);
    }
    __syncthreads();

    const int pbase = pb * PPB + tid;

    float x0[PPT], y0[PPT], x1[PPT], y1[PPT], ab[PPT], br[PPT];
#pragma unroll
    for (int j = 0; j < PPT; j++) {
        int p = pbase + j * NT;
        float cx, cy, w, h;
        if (p < P) {
            float2 c = locs[p];
            cx = c.x; cy = c.y;
            w = params[3 * p];
            h = params[3 * p + 1];
        } else {
            cx = -1e3f; cy = -1e3f; w = 0.0f; h = 0.0f;
        }
        x0[j] = cx - 0.5f * w;  x1[j] = cx + 0.5f * w;
        y0[j] = cy - 0.5f * h;  y1[j] = cy + 0.5f * h;
        ab[j] = w * h;
        br[j] = 0.0f;           // max r over t (r = inter/S, monotone in iou)
    }

    // ---- main loop: TWO truths per iteration for ILP (chains interleave) ----
    int tt = t0;
    for (; tt + 1 < t1; tt += 2) {
        const float4 tb0 = s_tr[tt - t0];
        const float4 tb1 = s_tr[tt - t0 + 1];
        const float  ta0 = s_ta[tt - t0];
        const float  ta1 = s_ta[tt - t0 + 1];

        float btr0 = 0.0f, btr1 = 0.0f;

#pragma unroll
        for (int j = 0; j < PPT; j++) {
            float dx0 = fminf(x1[j], tb0.z) - fmaxf(x0[j], tb0.x);
            float dy0 = fminf(y1[j], tb0.w) - fmaxf(y0[j], tb0.y);
            float dx1 = fminf(x1[j], tb1.z) - fmaxf(x0[j], tb1.x);
            float dy1 = fminf(y1[j], tb1.w) - fmaxf(y0[j], tb1.y);
            // single clamp: negative dy makes the product <=0, filtered by maxes
            float i0 = fmaxf(dx0, 0.0f) * dy0;
            float i1 = fmaxf(dx1, 0.0f) * dy1;
            float r0 = __fdividef(i0, ta0 + ab[j]);
            float r1 = __fdividef(i1, ta1 + ab[j]);
            br[j] = fmaxf(br[j], fmaxf(r0, r1));
            btr0  = fmaxf(btr0, r0);
            btr1  = fmaxf(btr1, r1);
        }

        // two interleaved warp maxes (independent chains)
        float a0 = btr0, a1 = btr1;
#pragma unroll
        for (int off = 16; off > 0; off >>= 1) {
            a0 = fmaxf(a0, __shfl_xor_sync(FULLM, a0, off));
            a1 = fmaxf(a1, __shfl_xor_sync(FULLM, a1, off));
        }
        unsigned b0 = __ballot_sync(FULLM, btr0 == a0);
        unsigned b1 = __ballot_sync(FULLM, btr1 == a1);
        if (lane == 0) {
            int base = pb * PPB + wid * 32;
            int pth0 = base + (__ffs(b0) - 1);
            int pth1 = base + (__ffs(b1) - 1);
            s_best[(tt - t0) * NWARP + wid] =
                (((unsigned long long)__float_as_uint(a0)) << 32) | (unsigned)(~pth0);
            s_best[(tt - t0 + 1) * NWARP + wid] =
                (((unsigned long long)__float_as_uint(a1)) << 32) | (unsigned)(~pth1);
        }
    }
    // odd tail
    for (; tt < t1; ++tt) {
        const float4 tb = s_tr[tt - t0];
        const float  ta = s_ta[tt - t0];
        float btr = 0.0f;
#pragma unroll
        for (int j = 0; j < PPT; j++) {
            float dx = fminf(x1[j], tb.z) - fmaxf(x0[j], tb.x);
            float dy = fminf(y1[j], tb.w) - fmaxf(y0[j], tb.y);
            float inter = fmaxf(dx, 0.0f) * dy;
            float r = __fdividef(inter, ta + ab[j]);
            br[j] = fmaxf(br[j], r);
            btr   = fmaxf(btr, r);
        }
        float mybtr = btr;
#pragma unroll
        for (int off = 16; off > 0; off >>= 1)
            btr = fmaxf(btr, __shfl_xor_sync(FULLM, btr, off));
        unsigned ball = __ballot_sync(FULLM, mybtr == btr);
        if (lane == 0) {
            int pth = pb * PPB + wid * 32 + (__ffs(ball) - 1);
            s_best[(tt - t0) * NWARP + wid] =
                (((unsigned long long)__float_as_uint(btr)) << 32) | (unsigned)(~pth);
        }
    }
    __syncthreads();

    // block combine + one global atomic per truth per block
    for (int t = t0 + tid; t < t1; t += NT) {
        unsigned long long m = s_best[(t - t0) * NWARP];
#pragma unroll
        for (int w = 1; w < NWARP; w++) {
            unsigned long long v = s_best[(t - t0) * NWARP + w];
            if (v > m) m = v;
        }
        atomicMax(&g_best[t], m);
    }

    // per-prior best overlap via float-bits atomicMax (values >= 0)
#pragma unroll
    for (int j = 0; j < PPT; j++) {
        int p = pbase + j * NT;
        if (p < P) atomicMax(&g_bto[p], __float_as_uint(br[j]));
    }

    // PDL: allow the dependent k_reduce to launch; its
    // cudaGridDependencySynchronize() still waits for this grid's completion.
    cudaTriggerProgrammaticLaunchCompletion();

    // ---- last block: resolve j + exact iou + last-t-wins scatter ----
    __threadfence();
    if (tid == 0)
        s_last = (atomicAdd(&g_ctr_main, 1u) == (unsigned)(nblocks - 1));
    __syncthreads();
    if (s_last) {
        __threadfence();
        for (int t = tid; t < T; t += NT) {
            unsigned long long m = g_best[t];
            unsigned int pth = (~((unsigned int)(m & 0xffffffffull))) & (MAXP - 1u);
            g_best[t] = 0ull;                      // restore zeros for next call
            float4 tb = truths[t];
            float ta = (tb.z - tb.x) * (tb.w - tb.y);
            // resolve j among the winning thread's PPT priors (smallest-j ties)
            float best_r = -1.0f, best_iou = 0.0f;
            unsigned best_p = pth;
#pragma unroll
            for (int j = 0; j < PPT; j++) {
                unsigned p = pth + (unsigned)(j * NT);
                if (p < (unsigned)P) {
                    float2 c = locs[p];
                    float w = params[3 * p];
                    float h = params[3 * p + 1];
                    float dx = fminf(c.x + 0.5f * w, tb.z) - fmaxf(c.x - 0.5f * w, tb.x);
                    float dy = fminf(c.y + 0.5f * h, tb.w) - fmaxf(c.y - 0.5f * h, tb.y);
                    float inter = fmaxf(dx, 0.0f) * fmaxf(dy, 0.0f);
                    float S = ta + w * h;
                    float r = inter / S;                       // exact
                    if (r > best_r) {
                        best_r = r;
                        best_p = p;
                        best_iou = inter / (S - inter);        // exact iou
                    }
                }
            }
            atomicMax(&g_scatter[best_p],
                (((unsigned long long)(t + 1)) << 32) | __float_as_uint(best_iou));
        }
        if (tid == 0) g_ctr_main = 0u;             // restore for next call
    }
}

__global__ void __launch_bounds__(NT)
k_reduce(const float* __restrict__ params,
         float* __restrict__ out, int P, int nblocks) {
    __shared__ float sh0[NWARP], sh1[NWARP], sh2[NWARP];
    __shared__ bool  s_last;
    const int tid  = threadIdx.x;
    const int lane = tid & 31;
    const int wid  = tid >> 5;
    const int p    = blockIdx.x * NT + tid;

    // ---- PDL preamble: runs while k_main is still executing ----
    float sig = 0.0f;
    if (p < P) {
        float a = params[3 * p + 2];               // input array: safe pre-sync
        sig = 1.0f / (1.0f + __expf(-a));
    }

    // Wait for k_main completion (memory of the primary grid fully visible)
    cudaGridDependencySynchronize();

    float s0 = 0.0f, s1 = 0.0f, s2 = 0.0f;
    if (p < P) {
        unsigned rb = g_bto[p];
        unsigned long long sc = g_scatter[p];
        g_bto[p] = 0u;                             // restore zeros for next call
        float r   = __uint_as_float(rb);
        float bto = __fdividef(r, 1.0f - r);       // r <= 0.5 always
        bool isbest = (sc != 0ull);
        if (isbest) {
            bto = __uint_as_float((unsigned int)(sc & 0xffffffffull));
            g_scatter[p] = 0ull;                   // restore zeros for next call
        }
        float xf = isbest ? 5.0f : (bto > 0.5f ? 1.0f : 0.0f);
        s0 = sig * xf * bto;
        s1 = sig;          // BETA = 1
        s2 = xf;
    }
#pragma unroll
    for (int off = 16; off > 0; off >>= 1) {
        s0 += __shfl_xor_sync(FULLM, s0, off);
        s1 += __shfl_xor_sync(FULLM, s1, off);
        s2 += __shfl_xor_sync(FULLM, s2, off);
    }
    if (lane == 0) { sh0[wid] = s0; sh1[wid] = s1; sh2[wid] = s2; }
    __syncthreads();
    if (wid == 0) {
        s0 = (lane < NWARP) ? sh0[lane] : 0.0f;
        s1 = (lane < NWARP) ? sh1[lane] : 0.0f;
        s2 = (lane < NWARP) ? sh2[lane] : 0.0f;
#pragma unroll
        for (int off = 4; off > 0; off >>= 1) {
            s0 += __shfl_xor_sync(FULLM, s0, off);
            s1 += __shfl_xor_sync(FULLM, s1, off);
            s2 += __shfl_xor_sync(FULLM, s2, off);
        }
        if (lane == 0) {
            atomicAdd(&g_sums[0], s0);
            atomicAdd(&g_sums[1], s1);
            atomicAdd(&g_sums[2], s2);
        }
    }

    __threadfence();
    if (tid == 0)
        s_last = (atomicAdd(&g_ctr_red, 1u) == (unsigned)(nblocks - 1));
    __syncthreads();
    if (s_last && tid == 0) {
        __threadfence();
        out[0] = (g_sums[0] + g_sums[1]) / g_sums[2];
        g_sums[0] = 0.0f; g_sums[1] = 0.0f; g_sums[2] = 0.0f;
        g_ctr_red = 0u;
    }
}

extern "C" void kernel_launch(void* const* d_in, const int* in_sizes, int n_in,
                              void* d_out, int out_size) {
    const float2* locs   = (const float2*)d_in[0];
    const float*  params = (const float*)d_in[1];
    const float4* truths = (const float4*)d_in[2];
    int P = in_sizes[0] / 2;
    int T = in_sizes[2] / 4;

    int tch     = (T + NTCH - 1) / NTCH;   // 43 for T=512
    int pblocks = (P + PPB - 1) / PPB;     // 37 for P=65536
    int nmain   = pblocks * NTCH;          // 444 = 148 SMs x occ 3 (single wave)

    k_main<<<nmain, NT>>>(locs, params, truths, P, T, pblocks, tch, nmain);

    // PDL launch: k_reduce blocks start once k_main triggers (before its tail),
    // preamble overlaps; cudaGridDependencySynchronize() enforces the data dep.
    int nred = (P + NT - 1) / NT;          // 256 blocks, 1 prior/thread
    {
        cudaLaunchConfig_t cfg = {};
        cfg.gridDim  = dim3((unsigned)nred, 1, 1);
        cfg.blockDim = dim3(NT, 1, 1);
        cfg.dynamicSmemBytes = 0;
        cudaLaunchAttribute attrs[1];
        attrs[0].id = cudaLaunchAttributeProgrammaticStreamSerialization;
        attrs[0].val.programmaticStreamSerializationAllowed = 1;
        cfg.attrs = attrs;
        cfg.numAttrs = 1;
        cudaLaunchKernelEx(&cfg, k_reduce, params, (float*)d_out, P, nred);
    }
}